// round 16
// baseline (speedup 1.0000x reference)
#include <cuda_runtime.h>
#include <cuda_bf16.h>
#include <cuda_fp16.h>
#include <cstdint>
#include <math.h>

#define NN 8192
#define FD 256
#define ALPHA_S 0.2f

// ---------------- device global scratch ----------------
__device__ __nv_bfloat16 g_hhi[NN * FD];
__device__ __nv_bfloat16 g_hlo[NN * FD];
__device__ __nv_bfloat16 g_WThi[FD * FD];
__device__ __nv_bfloat16 g_WTlo[FD * FD];
__device__ __half g_WhThi[FD * NN];   // Wh^T [n][k] fp16 hi/lo
__device__ __half g_WhTlo[FD * NN];
__device__ float g_f1[NN];
__device__ float g_f1p[8 * NN];
__device__ float g_f2p[8 * NN];
__device__ float g_rs[NN];
__device__ float2 g_tab2[NN];         // {exp(f2), exp(a*f2)}
__device__ uint32_t g_mask[(size_t)NN * 256];   // adj bitmask, 8 MB
__device__ uint32_t g_Bfrag[128 * 4 * 16 * 128]; // WhThi in MMA-frag order, 4 MB
__device__ unsigned int g_f2max_bits;

__device__ __forceinline__ unsigned int fkey(float f) {
    unsigned int b = __float_as_uint(f);
    return (b & 0x80000000u) ? ~b : (b | 0x80000000u);
}
__device__ __forceinline__ float fdec(unsigned int k) {
    unsigned int b = (k & 0x80000000u) ? (k & 0x7fffffffu) : ~k;
    return __uint_as_float(b);
}

// ---------------- PTX helpers ----------------
__device__ __forceinline__ uint32_t smem_u32(const void* p) {
    uint32_t a;
    asm("{ .reg .u64 t; cvta.to.shared.u64 t, %1; cvt.u32.u64 %0, t; }"
        : "=r"(a) : "l"(p));
    return a;
}
__device__ __forceinline__ void cp_async16(uint32_t dst, const void* src) {
    asm volatile("cp.async.cg.shared.global [%0], [%1], 16;"
                 :: "r"(dst), "l"(src) : "memory");
}
__device__ __forceinline__ void cp_commit() {
    asm volatile("cp.async.commit_group;" ::: "memory");
}
template<int N>
__device__ __forceinline__ void cp_wait() {
    asm volatile("cp.async.wait_group %0;" :: "n"(N) : "memory");
}
__device__ __forceinline__ void ldm_x4(uint32_t addr, uint32_t& r0, uint32_t& r1,
                                       uint32_t& r2, uint32_t& r3) {
    asm volatile("ldmatrix.sync.aligned.m8n8.x4.shared.b16 {%0,%1,%2,%3}, [%4];"
                 : "=r"(r0), "=r"(r1), "=r"(r2), "=r"(r3) : "r"(addr));
}
__device__ __forceinline__ void mma_bf16(float* c, const uint32_t* a, const uint32_t* b) {
    asm volatile(
        "mma.sync.aligned.m16n8k16.row.col.f32.bf16.bf16.f32 "
        "{%0,%1,%2,%3}, {%4,%5,%6,%7}, {%8,%9}, {%0,%1,%2,%3};"
        : "+f"(c[0]), "+f"(c[1]), "+f"(c[2]), "+f"(c[3])
        : "r"(a[0]), "r"(a[1]), "r"(a[2]), "r"(a[3]), "r"(b[0]), "r"(b[1]));
}
__device__ __forceinline__ void mma_fp16(float* c, const uint32_t* a, const uint32_t* b) {
    asm volatile(
        "mma.sync.aligned.m16n8k16.row.col.f32.f16.f16.f32 "
        "{%0,%1,%2,%3}, {%4,%5,%6,%7}, {%8,%9}, {%0,%1,%2,%3};"
        : "+f"(c[0]), "+f"(c[1]), "+f"(c[2]), "+f"(c[3])
        : "r"(a[0]), "r"(a[1]), "r"(a[2]), "r"(a[3]), "r"(b[0]), "r"(b[1]));
}

// ======================= GEMM1: Wh = h @ W (bf16 3-pass) ====
static constexpr int ROWB    = 80;
static constexpr int TILE_B  = 128 * ROWB;
static constexpr int STAGE_B = 4 * TILE_B;
static constexpr int SMEM1_SZ = 2 * STAGE_B;      // 81920

template<int KCHUNKS>
__global__ void __launch_bounds__(256, 1) mma_gemm1(
    const __nv_bfloat16* __restrict__ Ahi, const __nv_bfloat16* __restrict__ Alo,
    const __nv_bfloat16* __restrict__ Bhi, const __nv_bfloat16* __restrict__ Blo,
    __half* __restrict__ ThiOut, __half* __restrict__ TloOut)
{
    constexpr int K = KCHUNKS * 32;
    extern __shared__ char smem[];
    const uint32_t sb = smem_u32(smem);

    const int tid  = threadIdx.x;
    const int warp = tid >> 5;
    const int lane = tid & 31;
    const int wm   = warp & 3;
    const int wn   = warp >> 2;
    const int row0 = blockIdx.x * 128;
    const int col0 = blockIdx.y * 128;

    const int a_row = lane & 15;
    const int a_kb  = (lane >> 4) * 16;
    const int b_row = ((lane >> 4) << 3) + (lane & 7);
    const int b_kb  = ((lane >> 3) & 1) * 16;
    const int lrow = tid >> 2;
    const int lch  = tid & 3;

    float acc[2][8][4];
    #pragma unroll
    for (int i = 0; i < 2; i++)
        #pragma unroll
        for (int j = 0; j < 8; j++)
            #pragma unroll
            for (int q = 0; q < 4; q++) acc[i][j][q] = 0.0f;

    auto load_stage = [&](int s, int kc) {
        const uint32_t base = sb + s * STAGE_B;
        const int k0 = kc * 32;
        #pragma unroll
        for (int it = 0; it < 2; it++) {
            int r = lrow + it * 64;
            uint32_t doff = r * ROWB + lch * 16;
            size_t ga = (size_t)(row0 + r) * K + k0 + lch * 8;
            size_t gb = (size_t)(col0 + r) * K + k0 + lch * 8;
            cp_async16(base + 0 * TILE_B + doff, Ahi + ga);
            cp_async16(base + 1 * TILE_B + doff, Alo + ga);
            cp_async16(base + 2 * TILE_B + doff, Bhi + gb);
            cp_async16(base + 3 * TILE_B + doff, Blo + gb);
        }
        cp_commit();
    };

    load_stage(0, 0);

    for (int c = 0; c < KCHUNKS; c++) {
        const int s = c & 1;
        if (c + 1 < KCHUNKS) { load_stage(s ^ 1, c + 1); cp_wait<1>(); }
        else                 { cp_wait<0>(); }
        __syncthreads();

        const uint32_t base = sb + s * STAGE_B;
        #pragma unroll
        for (int ks = 0; ks < 2; ks++) {
            const int kb = ks * 32;
            uint32_t ah[2][4], al[2][4], bh[16], bl[16];
            #pragma unroll
            for (int mt = 0; mt < 2; mt++) {
                uint32_t ra = (wm * 32 + mt * 16 + a_row) * ROWB + kb + a_kb;
                ldm_x4(base + 0 * TILE_B + ra, ah[mt][0], ah[mt][1], ah[mt][2], ah[mt][3]);
                ldm_x4(base + 1 * TILE_B + ra, al[mt][0], al[mt][1], al[mt][2], al[mt][3]);
            }
            #pragma unroll
            for (int nb = 0; nb < 4; nb++) {
                uint32_t rb = (wn * 64 + nb * 16 + b_row) * ROWB + kb + b_kb;
                ldm_x4(base + 2 * TILE_B + rb, bh[4*nb], bh[4*nb+1], bh[4*nb+2], bh[4*nb+3]);
                ldm_x4(base + 3 * TILE_B + rb, bl[4*nb], bl[4*nb+1], bl[4*nb+2], bl[4*nb+3]);
            }
            #pragma unroll
            for (int mt = 0; mt < 2; mt++)
                #pragma unroll
                for (int nt = 0; nt < 8; nt++) {
                    mma_bf16(acc[mt][nt], ah[mt], bh + 2*nt);
                    mma_bf16(acc[mt][nt], ah[mt], bl + 2*nt);
                    mma_bf16(acc[mt][nt], al[mt], bh + 2*nt);
                }
        }
        __syncthreads();
    }

    constexpr int TST = 272;
    __half* shT = (__half*)smem;
    __half* slT = (__half*)(smem + 128 * TST);
    #pragma unroll
    for (int mt = 0; mt < 2; mt++) {
        #pragma unroll
        for (int nt = 0; nt < 8; nt++) {
            int ml = wm * 32 + mt * 16 + (lane >> 2);
            int nl = wn * 64 + nt * 8 + (lane & 3) * 2;
            #pragma unroll
            for (int q = 0; q < 4; q++) {
                int m = ml + (q >> 1) * 8;
                int n = nl + (q & 1);
                float v = acc[mt][nt][q];
                __half hb = __float2half_rn(v);
                __half lb = __float2half_rn(v - __half2float(hb));
                shT[n * 136 + m] = hb;
                slT[n * 136 + m] = lb;
            }
        }
    }
    __syncthreads();
    #pragma unroll
    for (int it = 0; it < 8; it++) {
        int idx = tid + it * 256;
        int n = idx >> 4, cm = idx & 15;
        uint4 vh = *(uint4*)(smem + n * TST + cm * 16);
        uint4 vl = *(uint4*)(smem + 128 * TST + n * TST + cm * 16);
        size_t g = (size_t)(col0 + n) * NN + row0 + cm * 8;
        *(uint4*)(ThiOut + g) = vh;
        *(uint4*)(TloOut + g) = vl;
    }
}

// ============ convert + pack merged (both smem-free, DRAM-bound) ==========
__global__ void __launch_bounds__(256) convert_pack(
    const float* __restrict__ h, const float* __restrict__ W,
    const int* __restrict__ adj)
{
    if (blockIdx.x >= NN + FD) {
        const int row  = blockIdx.x - (NN + FD);
        const int lane = threadIdx.x & 31;
        const int w    = threadIdx.x >> 5;
        const size_t base = (size_t)row * NN;
        #pragma unroll 8
        for (int it = 0; it < 32; it++) {
            int word = w * 32 + it;
            int v = adj[base + word * 32 + lane];
            uint32_t b = __ballot_sync(0xffffffffu, v > 0);
            if (lane == 0) g_mask[(size_t)row * 256 + word] = b;
        }
        return;
    }
    if (blockIdx.x == 0 && threadIdx.x == 0) g_f2max_bits = 0u;
    int t = blockIdx.x * 256 + threadIdx.x;
    if (blockIdx.x < NN) {
        float v = h[t];
        __nv_bfloat16 hb = __float2bfloat16(v);
        g_hhi[t] = hb;
        g_hlo[t] = __float2bfloat16(v - __bfloat162float(hb));
    } else {
        int idx = t - NN * 256;
        int o = idx >> 8, i = idx & 255;
        float v = W[i * FD + o];
        __nv_bfloat16 hb = __float2bfloat16(v);
        g_WThi[idx] = hb;
        g_WTlo[idx] = __float2bfloat16(v - __bfloat162float(hb));
    }
}

// ============ WhThi -> MMA fragment order (layout by construction) ========
static constexpr int TF_SMEM = 4 * 64 * 144;   // 36864

__global__ void __launch_bounds__(512) bfrag_kernel()
{
    extern __shared__ char smem[];
    const uint32_t sb = smem_u32(smem);
    const int tid  = threadIdx.x;
    const int warp = tid >> 5;
    const int lane = tid & 31;
    const int c    = blockIdx.x;
    const int wn   = warp & 3;
    const int ks   = warp >> 2;

    for (int idx = tid; idx < 2048; idx += 512) {
        int g  = idx >> 9;
        int n  = (idx >> 3) & 63;
        int c8 = idx & 7;
        uint4 v = *(const uint4*)(g_WhThi + (size_t)(g * 64 + n) * NN + c * 64 + c8 * 8);
        *(uint4*)(smem + g * 9216 + n * 144 + c8 * 16) = v;
    }
    __syncthreads();

    const int b_row = ((lane >> 4) << 3) + (lane & 7);
    const int b_kb  = ((lane >> 3) & 1) * 16;
    #pragma unroll
    for (int nb = 0; nb < 4; nb++) {
        uint32_t r0, r1, r2, r3;
        uint32_t rb = sb + wn * 9216 + (nb * 16 + b_row) * 144 + ks * 32 + b_kb;
        ldm_x4(rb, r0, r1, r2, r3);
        uint4* outp = (uint4*)g_Bfrag +
                      ((size_t)(c * 4 + wn) * 16 + ks * 4 + nb) * 32 + lane;
        *outp = make_uint4(r0, r1, r2, r3);
    }
}

// ======================= fused (P @ Wh)/rs + ELU ==========================
// 256 threads (4 wm x 2 wn), N=128 per CTA, grid (128,2), 2 CTAs/SM.
// NO smem, NO barriers anywhere. rowsum precomputed in g_rs.
__device__ __forceinline__ uint32_t pack2(float a, float b) {
    __half2 h = __floats2half2_rn(a, b);
    return *(uint32_t*)&h;
}

__global__ void __launch_bounds__(256, 2) fused_gemm2(float* __restrict__ out)
{
    const int tid  = threadIdx.x;
    const int warp = tid >> 5;
    const int lane = tid & 31;
    const int wm   = warp & 3;
    const int wn   = warp >> 2;                   // 0..1
    const int grp  = blockIdx.y * 2 + wn;         // 0..3 (cols grp*64)
    const int lq   = lane & 3;
    const int row0 = blockIdx.x * 64;
    const int r0l  = wm * 16 + (lane >> 2);

    const float f2max = fdec(g_f2max_bits);
    const float f10 = g_f1[row0 + r0l];
    const float f11 = g_f1[row0 + r0l + 8];
    float tt;
    tt = f10 + f2max; const float Cr0 = tt > 0.f ? tt : ALPHA_S * tt;
    tt = f11 + f2max; const float Cr1 = tt > 0.f ? tt : ALPHA_S * tt;
    const float c1p0 = __expf(f10 - Cr0), c1n0 = __expf(ALPHA_S * f10 - Cr0);
    const float c1p1 = __expf(f11 - Cr1), c1n1 = __expf(ALPHA_S * f11 - Cr1);

    const uint32_t* mrow0 = g_mask + (size_t)(row0 + r0l) * 256;
    const uint32_t* mrow1 = g_mask + (size_t)(row0 + r0l + 8) * 256;

    float acc[8][4];
    #pragma unroll
    for (int j = 0; j < 8; j++)
        #pragma unroll
        for (int q = 0; q < 4; q++) acc[j][q] = 0.0f;

    for (int c = 0; c < 128; c++) {
        const uint64_t m0 = *(const uint64_t*)(mrow0 + c * 2);
        const uint64_t m1 = *(const uint64_t*)(mrow1 + c * 2);
        const float4* tb = (const float4*)(g_tab2 + c * 64);
        const uint4* bp = (const uint4*)g_Bfrag + ((size_t)(c * 4 + grp) * 16) * 32 + lane;

        #pragma unroll
        for (int ks = 0; ks < 4; ks++) {
            uint4 q0 = __ldg(bp + (ks * 4 + 0) * 32);
            uint4 q1 = __ldg(bp + (ks * 4 + 1) * 32);
            uint4 q2 = __ldg(bp + (ks * 4 + 2) * 32);
            uint4 q3 = __ldg(bp + (ks * 4 + 3) * 32);

            const int colb = ks * 16 + 2 * lq;
            float4 ta = __ldg(tb + (colb >> 1));
            float4 tc = __ldg(tb + ((colb + 8) >> 1));
            uint32_t b0 = (uint32_t)(m0 >> colb);
            uint32_t b1 = (uint32_t)(m1 >> colb);
            float p00 = (b0 & 1u)     ? fmaxf(c1p0 * ta.x, c1n0 * ta.y) : 0.f;
            float p01 = (b0 & 2u)     ? fmaxf(c1p0 * ta.z, c1n0 * ta.w) : 0.f;
            float p08 = (b0 & 0x100u) ? fmaxf(c1p0 * tc.x, c1n0 * tc.y) : 0.f;
            float p09 = (b0 & 0x200u) ? fmaxf(c1p0 * tc.z, c1n0 * tc.w) : 0.f;
            float p10 = (b1 & 1u)     ? fmaxf(c1p1 * ta.x, c1n1 * ta.y) : 0.f;
            float p11 = (b1 & 2u)     ? fmaxf(c1p1 * ta.z, c1n1 * ta.w) : 0.f;
            float p18 = (b1 & 0x100u) ? fmaxf(c1p1 * tc.x, c1n1 * tc.y) : 0.f;
            float p19 = (b1 & 0x200u) ? fmaxf(c1p1 * tc.z, c1n1 * tc.w) : 0.f;
            uint32_t af[4];
            af[0] = pack2(p00, p01);
            af[1] = pack2(p10, p11);
            af[2] = pack2(p08, p09);
            af[3] = pack2(p18, p19);

            uint32_t bh[16] = { q0.x, q0.y, q0.z, q0.w,
                                q1.x, q1.y, q1.z, q1.w,
                                q2.x, q2.y, q2.z, q2.w,
                                q3.x, q3.y, q3.z, q3.w };
            #pragma unroll
            for (int nt = 0; nt < 8; nt++)
                mma_fp16(acc[nt], af, bh + 2 * nt);
        }
    }

    const float invA = 1.0f / g_rs[row0 + r0l];
    const float invB = 1.0f / g_rs[row0 + r0l + 8];
    #pragma unroll
    for (int nt = 0; nt < 8; nt++) {
        int cc = grp * 64 + nt * 8 + lq * 2;
        float v0 = acc[nt][0] * invA;
        float v1 = acc[nt][1] * invA;
        float v2 = acc[nt][2] * invB;
        float v3 = acc[nt][3] * invB;
        float2 oA = { v0 > 0.f ? v0 : expm1f(v0), v1 > 0.f ? v1 : expm1f(v1) };
        float2 oB = { v2 > 0.f ? v2 : expm1f(v2), v3 > 0.f ? v3 : expm1f(v3) };
        *(float2*)(out + (size_t)(row0 + r0l) * FD + cc) = oA;
        *(float2*)(out + (size_t)(row0 + r0l + 8) * FD + cc) = oB;
    }
}

// ------------- rowsum: rs[r] = sum_j mask * max(cp*e^f2, cn*e^af2) --------
// 512 threads = 16 warps; warp handles 2 rows; grid 256. Deterministic.
__global__ void __launch_bounds__(512) rowsum_kernel()
{
    const int warp = threadIdx.x >> 5;
    const int lane = threadIdx.x & 31;
    const int r0 = (blockIdx.x * 16 + warp) * 2;

    const float f2max = fdec(g_f2max_bits);
    const float f1a = g_f1[r0];
    const float f1b = g_f1[r0 + 1];
    float tt;
    tt = f1a + f2max; const float CrA = tt > 0.f ? tt : ALPHA_S * tt;
    tt = f1b + f2max; const float CrB = tt > 0.f ? tt : ALPHA_S * tt;
    const float cpA = __expf(f1a - CrA), cnA = __expf(ALPHA_S * f1a - CrA);
    const float cpB = __expf(f1b - CrB), cnB = __expf(ALPHA_S * f1b - CrB);

    const uint4* mA = (const uint4*)(g_mask + (size_t)r0 * 256);
    const uint4* mB = (const uint4*)(g_mask + (size_t)(r0 + 1) * 256);

    float sA = 0.f, sB = 0.f;
    for (int w4 = 0; w4 < 64; w4++) {
        uint4 wa = __ldg(mA + w4);
        uint4 wb = __ldg(mB + w4);
        uint32_t wordsA[4] = { wa.x, wa.y, wa.z, wa.w };
        uint32_t wordsB[4] = { wb.x, wb.y, wb.z, wb.w };
        #pragma unroll
        for (int k = 0; k < 4; k++) {
            float2 t = __ldg(g_tab2 + (w4 * 4 + k) * 32 + lane);
            float pv = fmaxf(cpA * t.x, cnA * t.y);
            float qv = fmaxf(cpB * t.x, cnB * t.y);
            if ((wordsA[k] >> lane) & 1u) sA += pv;
            if ((wordsB[k] >> lane) & 1u) sB += qv;
        }
    }
    #pragma unroll
    for (int o = 16; o > 0; o >>= 1) {
        sA += __shfl_xor_sync(0xffffffffu, sA, o);
        sB += __shfl_xor_sync(0xffffffffu, sB, o);
    }
    if (lane == 0) { g_rs[r0] = sA; g_rs[r0 + 1] = sB; }
}

// ------- f1/f2 partials: coalesced WhT row reads, 8 n-slices ----------
__global__ void __launch_bounds__(256) f1f2_kernel(const float* __restrict__ a)
{
    const int tid   = threadIdx.x;
    const int mblk  = blockIdx.x >> 3;
    const int slice = blockIdx.x & 7;
    const int m     = mblk * 256 + tid;

    float s1 = 0.0f, s2 = 0.0f;
    #pragma unroll 8
    for (int i = 0; i < 32; i++) {
        int n = slice * 32 + i;
        float v = __half2float(g_WhThi[(size_t)n * NN + m]) +
                  __half2float(g_WhTlo[(size_t)n * NN + m]);
        s1 = fmaf(v, __ldg(a + n),      s1);
        s2 = fmaf(v, __ldg(a + FD + n), s2);
    }
    g_f1p[slice * NN + m] = s1;
    g_f2p[slice * NN + m] = s2;
}

// ------- combine partials + exp tables + global f2 max -------
__global__ void __launch_bounds__(256) tab_kernel()
{
    __shared__ float red[256];
    int tid = threadIdx.x;
    int m = blockIdx.x * 256 + tid;
    float f1 = 0.f, f2 = 0.f;
    #pragma unroll
    for (int s = 0; s < 8; s++) {
        f1 += g_f1p[s * NN + m];
        f2 += g_f2p[s * NN + m];
    }
    g_f1[m] = f1;
    float s2c = fminf(f2, 60.f);
    g_tab2[m] = make_float2(__expf(s2c), __expf(ALPHA_S * s2c));

    red[tid] = f2; __syncthreads();
    #pragma unroll
    for (int s = 128; s > 0; s >>= 1) {
        if (tid < s) red[tid] = fmaxf(red[tid], red[tid + s]);
        __syncthreads();
    }
    if (tid == 0) atomicMax(&g_f2max_bits, fkey(red[0]));
}

// ---------------- launch ----------------
extern "C" void kernel_launch(void* const* d_in, const int* in_sizes, int n_in,
                              void* d_out, int out_size)
{
    const float* h   = (const float*)d_in[0];
    const int*   adj = (const int*)  d_in[1];
    const float* W   = (const float*)d_in[3];
    const float* a   = (const float*)d_in[4];
    float* out = (float*)d_out;

    __nv_bfloat16 *phhi, *phlo, *pWThi, *pWTlo;
    __half *pWhThi, *pWhTlo;
    cudaGetSymbolAddress((void**)&phhi,   g_hhi);
    cudaGetSymbolAddress((void**)&phlo,   g_hlo);
    cudaGetSymbolAddress((void**)&pWThi,  g_WThi);
    cudaGetSymbolAddress((void**)&pWTlo,  g_WTlo);
    cudaGetSymbolAddress((void**)&pWhThi, g_WhThi);
    cudaGetSymbolAddress((void**)&pWhTlo, g_WhTlo);

    cudaFuncSetAttribute(mma_gemm1<8>, cudaFuncAttributeMaxDynamicSharedMemorySize, SMEM1_SZ);
    cudaFuncSetAttribute(bfrag_kernel, cudaFuncAttributeMaxDynamicSharedMemorySize, TF_SMEM);

    // 1) h/W^T splits + adj bitmask pack, merged (both smem-free, DRAM-bound)
    convert_pack<<<NN + FD + NN, 256>>>(h, W, adj);

    // 2) Wh = h@W (bf16 3-pass)
    {
        dim3 grid(NN / 128, FD / 128);
        mma_gemm1<8><<<grid, 256, SMEM1_SZ>>>(
            phhi, phlo, pWThi, pWTlo, pWhThi, pWhTlo);
    }

    // 2b) permute WhThi into MMA-fragment order
    bfrag_kernel<<<128, 512, TF_SMEM>>>();

    // 3) f1/f2 partials (8 slices), combine + tables + f2max, then rowsums
    f1f2_kernel<<<256, 256>>>(a);
    tab_kernel<<<NN / 256, 256>>>();
    rowsum_kernel<<<NN / 32, 512>>>();

    // 4) fused (P @ Wh)/rs + ELU — 2 CTAs/SM, zero barriers/smem
    {
        dim3 grid(NN / 64, 2);
        fused_gemm2<<<grid, 256>>>(out);
    }
}

// round 17
// speedup vs baseline: 1.0838x; 1.0838x over previous
#include <cuda_runtime.h>
#include <cuda_bf16.h>
#include <cuda_fp16.h>
#include <cstdint>
#include <math.h>

#define NN 8192
#define FD 256
#define ALPHA_S 0.2f

// ---------------- device global scratch ----------------
__device__ __nv_bfloat16 g_hhi[NN * FD];
__device__ __nv_bfloat16 g_hlo[NN * FD];
__device__ __nv_bfloat16 g_WThi[FD * FD];
__device__ __nv_bfloat16 g_WTlo[FD * FD];
__device__ __half g_WhThi[FD * NN];   // Wh^T [n][k] fp16 hi/lo
__device__ __half g_WhTlo[FD * NN];
__device__ float g_f1[NN];
__device__ float g_f1p[8 * NN];
__device__ float g_f2p[8 * NN];
__device__ float2 g_tab2[NN];         // {exp(f2), exp(a*f2)}
__device__ uint32_t g_mask[(size_t)NN * 256];   // adj bitmask, 8 MB
__device__ uint32_t g_Bfrag[128 * 4 * 16 * 128]; // WhThi in MMA-frag order, 4 MB
__device__ unsigned int g_f2max_bits;

__device__ __forceinline__ unsigned int fkey(float f) {
    unsigned int b = __float_as_uint(f);
    return (b & 0x80000000u) ? ~b : (b | 0x80000000u);
}
__device__ __forceinline__ float fdec(unsigned int k) {
    unsigned int b = (k & 0x80000000u) ? (k & 0x7fffffffu) : ~k;
    return __uint_as_float(b);
}

// ---------------- PTX helpers ----------------
__device__ __forceinline__ uint32_t smem_u32(const void* p) {
    uint32_t a;
    asm("{ .reg .u64 t; cvta.to.shared.u64 t, %1; cvt.u32.u64 %0, t; }"
        : "=r"(a) : "l"(p));
    return a;
}
__device__ __forceinline__ void cp_async16(uint32_t dst, const void* src) {
    asm volatile("cp.async.cg.shared.global [%0], [%1], 16;"
                 :: "r"(dst), "l"(src) : "memory");
}
__device__ __forceinline__ void cp_commit() {
    asm volatile("cp.async.commit_group;" ::: "memory");
}
template<int N>
__device__ __forceinline__ void cp_wait() {
    asm volatile("cp.async.wait_group %0;" :: "n"(N) : "memory");
}
__device__ __forceinline__ void ldm_x4(uint32_t addr, uint32_t& r0, uint32_t& r1,
                                       uint32_t& r2, uint32_t& r3) {
    asm volatile("ldmatrix.sync.aligned.m8n8.x4.shared.b16 {%0,%1,%2,%3}, [%4];"
                 : "=r"(r0), "=r"(r1), "=r"(r2), "=r"(r3) : "r"(addr));
}
__device__ __forceinline__ void mma_bf16(float* c, const uint32_t* a, const uint32_t* b) {
    asm volatile(
        "mma.sync.aligned.m16n8k16.row.col.f32.bf16.bf16.f32 "
        "{%0,%1,%2,%3}, {%4,%5,%6,%7}, {%8,%9}, {%0,%1,%2,%3};"
        : "+f"(c[0]), "+f"(c[1]), "+f"(c[2]), "+f"(c[3])
        : "r"(a[0]), "r"(a[1]), "r"(a[2]), "r"(a[3]), "r"(b[0]), "r"(b[1]));
}
__device__ __forceinline__ void mma_fp16(float* c, const uint32_t* a, const uint32_t* b) {
    asm volatile(
        "mma.sync.aligned.m16n8k16.row.col.f32.f16.f16.f32 "
        "{%0,%1,%2,%3}, {%4,%5,%6,%7}, {%8,%9}, {%0,%1,%2,%3};"
        : "+f"(c[0]), "+f"(c[1]), "+f"(c[2]), "+f"(c[3])
        : "r"(a[0]), "r"(a[1]), "r"(a[2]), "r"(a[3]), "r"(b[0]), "r"(b[1]));
}

// ======================= GEMM1: Wh = h @ W (bf16 3-pass) ====
static constexpr int ROWB    = 80;
static constexpr int TILE_B  = 128 * ROWB;
static constexpr int STAGE_B = 4 * TILE_B;
static constexpr int SMEM1_SZ = 2 * STAGE_B;      // 81920

template<int KCHUNKS>
__global__ void __launch_bounds__(256, 1) mma_gemm1(
    const __nv_bfloat16* __restrict__ Ahi, const __nv_bfloat16* __restrict__ Alo,
    const __nv_bfloat16* __restrict__ Bhi, const __nv_bfloat16* __restrict__ Blo,
    __half* __restrict__ ThiOut, __half* __restrict__ TloOut)
{
    constexpr int K = KCHUNKS * 32;
    extern __shared__ char smem[];
    const uint32_t sb = smem_u32(smem);

    const int tid  = threadIdx.x;
    const int warp = tid >> 5;
    const int lane = tid & 31;
    const int wm   = warp & 3;
    const int wn   = warp >> 2;
    const int row0 = blockIdx.x * 128;
    const int col0 = blockIdx.y * 128;

    const int a_row = lane & 15;
    const int a_kb  = (lane >> 4) * 16;
    const int b_row = ((lane >> 4) << 3) + (lane & 7);
    const int b_kb  = ((lane >> 3) & 1) * 16;
    const int lrow = tid >> 2;
    const int lch  = tid & 3;

    float acc[2][8][4];
    #pragma unroll
    for (int i = 0; i < 2; i++)
        #pragma unroll
        for (int j = 0; j < 8; j++)
            #pragma unroll
            for (int q = 0; q < 4; q++) acc[i][j][q] = 0.0f;

    auto load_stage = [&](int s, int kc) {
        const uint32_t base = sb + s * STAGE_B;
        const int k0 = kc * 32;
        #pragma unroll
        for (int it = 0; it < 2; it++) {
            int r = lrow + it * 64;
            uint32_t doff = r * ROWB + lch * 16;
            size_t ga = (size_t)(row0 + r) * K + k0 + lch * 8;
            size_t gb = (size_t)(col0 + r) * K + k0 + lch * 8;
            cp_async16(base + 0 * TILE_B + doff, Ahi + ga);
            cp_async16(base + 1 * TILE_B + doff, Alo + ga);
            cp_async16(base + 2 * TILE_B + doff, Bhi + gb);
            cp_async16(base + 3 * TILE_B + doff, Blo + gb);
        }
        cp_commit();
    };

    load_stage(0, 0);

    for (int c = 0; c < KCHUNKS; c++) {
        const int s = c & 1;
        if (c + 1 < KCHUNKS) { load_stage(s ^ 1, c + 1); cp_wait<1>(); }
        else                 { cp_wait<0>(); }
        __syncthreads();

        const uint32_t base = sb + s * STAGE_B;
        #pragma unroll
        for (int ks = 0; ks < 2; ks++) {
            const int kb = ks * 32;
            uint32_t ah[2][4], al[2][4], bh[16], bl[16];
            #pragma unroll
            for (int mt = 0; mt < 2; mt++) {
                uint32_t ra = (wm * 32 + mt * 16 + a_row) * ROWB + kb + a_kb;
                ldm_x4(base + 0 * TILE_B + ra, ah[mt][0], ah[mt][1], ah[mt][2], ah[mt][3]);
                ldm_x4(base + 1 * TILE_B + ra, al[mt][0], al[mt][1], al[mt][2], al[mt][3]);
            }
            #pragma unroll
            for (int nb = 0; nb < 4; nb++) {
                uint32_t rb = (wn * 64 + nb * 16 + b_row) * ROWB + kb + b_kb;
                ldm_x4(base + 2 * TILE_B + rb, bh[4*nb], bh[4*nb+1], bh[4*nb+2], bh[4*nb+3]);
                ldm_x4(base + 3 * TILE_B + rb, bl[4*nb], bl[4*nb+1], bl[4*nb+2], bl[4*nb+3]);
            }
            #pragma unroll
            for (int mt = 0; mt < 2; mt++)
                #pragma unroll
                for (int nt = 0; nt < 8; nt++) {
                    mma_bf16(acc[mt][nt], ah[mt], bh + 2*nt);
                    mma_bf16(acc[mt][nt], ah[mt], bl + 2*nt);
                    mma_bf16(acc[mt][nt], al[mt], bh + 2*nt);
                }
        }
        __syncthreads();
    }

    constexpr int TST = 272;
    __half* shT = (__half*)smem;
    __half* slT = (__half*)(smem + 128 * TST);
    #pragma unroll
    for (int mt = 0; mt < 2; mt++) {
        #pragma unroll
        for (int nt = 0; nt < 8; nt++) {
            int ml = wm * 32 + mt * 16 + (lane >> 2);
            int nl = wn * 64 + nt * 8 + (lane & 3) * 2;
            #pragma unroll
            for (int q = 0; q < 4; q++) {
                int m = ml + (q >> 1) * 8;
                int n = nl + (q & 1);
                float v = acc[mt][nt][q];
                __half hb = __float2half_rn(v);
                __half lb = __float2half_rn(v - __half2float(hb));
                shT[n * 136 + m] = hb;
                slT[n * 136 + m] = lb;
            }
        }
    }
    __syncthreads();
    #pragma unroll
    for (int it = 0; it < 8; it++) {
        int idx = tid + it * 256;
        int n = idx >> 4, cm = idx & 15;
        uint4 vh = *(uint4*)(smem + n * TST + cm * 16);
        uint4 vl = *(uint4*)(smem + 128 * TST + n * TST + cm * 16);
        size_t g = (size_t)(col0 + n) * NN + row0 + cm * 8;
        *(uint4*)(ThiOut + g) = vh;
        *(uint4*)(TloOut + g) = vl;
    }
}

// ============ convert + pack merged (both smem-free, DRAM-bound) ==========
__global__ void __launch_bounds__(256) convert_pack(
    const float* __restrict__ h, const float* __restrict__ W,
    const int* __restrict__ adj)
{
    if (blockIdx.x >= NN + FD) {
        const int row  = blockIdx.x - (NN + FD);
        const int lane = threadIdx.x & 31;
        const int w    = threadIdx.x >> 5;
        const size_t base = (size_t)row * NN;
        #pragma unroll 8
        for (int it = 0; it < 32; it++) {
            int word = w * 32 + it;
            int v = adj[base + word * 32 + lane];
            uint32_t b = __ballot_sync(0xffffffffu, v > 0);
            if (lane == 0) g_mask[(size_t)row * 256 + word] = b;
        }
        return;
    }
    if (blockIdx.x == 0 && threadIdx.x == 0) g_f2max_bits = 0u;
    int t = blockIdx.x * 256 + threadIdx.x;
    if (blockIdx.x < NN) {
        float v = h[t];
        __nv_bfloat16 hb = __float2bfloat16(v);
        g_hhi[t] = hb;
        g_hlo[t] = __float2bfloat16(v - __bfloat162float(hb));
    } else {
        int idx = t - NN * 256;
        int o = idx >> 8, i = idx & 255;
        float v = W[i * FD + o];
        __nv_bfloat16 hb = __float2bfloat16(v);
        g_WThi[idx] = hb;
        g_WTlo[idx] = __float2bfloat16(v - __bfloat162float(hb));
    }
}

// ============ WhThi -> MMA fragment order (layout by construction) ========
static constexpr int TF_SMEM = 4 * 64 * 144;   // 36864

__global__ void __launch_bounds__(512) bfrag_kernel()
{
    extern __shared__ char smem[];
    const uint32_t sb = smem_u32(smem);
    const int tid  = threadIdx.x;
    const int warp = tid >> 5;
    const int lane = tid & 31;
    const int c    = blockIdx.x;
    const int wn   = warp & 3;
    const int ks   = warp >> 2;

    for (int idx = tid; idx < 2048; idx += 512) {
        int g  = idx >> 9;
        int n  = (idx >> 3) & 63;
        int c8 = idx & 7;
        uint4 v = *(const uint4*)(g_WhThi + (size_t)(g * 64 + n) * NN + c * 64 + c8 * 8);
        *(uint4*)(smem + g * 9216 + n * 144 + c8 * 16) = v;
    }
    __syncthreads();

    const int b_row = ((lane >> 4) << 3) + (lane & 7);
    const int b_kb  = ((lane >> 3) & 1) * 16;
    #pragma unroll
    for (int nb = 0; nb < 4; nb++) {
        uint32_t r0, r1, r2, r3;
        uint32_t rb = sb + wn * 9216 + (nb * 16 + b_row) * 144 + ks * 32 + b_kb;
        ldm_x4(rb, r0, r1, r2, r3);
        uint4* outp = (uint4*)g_Bfrag +
                      ((size_t)(c * 4 + wn) * 16 + ks * 4 + nb) * 32 + lane;
        *outp = make_uint4(r0, r1, r2, r3);
    }
}

// ======================= fused softmax + P@Wh GEMM ========================
// R15: 512 threads (4 wm x 4 wn), M=64 x N=256, 128 chunks of K=64.
// B frags via direct LDG.128 from g_Bfrag; A frags in registers; in-kernel
// rowsum; ZERO barriers in the main loop (one __syncthreads total).
__device__ __forceinline__ uint32_t pack2(float a, float b) {
    __half2 h = __floats2half2_rn(a, b);
    return *(uint32_t*)&h;
}

__global__ void __launch_bounds__(512, 1) fused_gemm2(float* __restrict__ out)
{
    __shared__ float rs[64];
    const int tid  = threadIdx.x;
    const int warp = tid >> 5;
    const int lane = tid & 31;
    const int wm   = warp & 3;
    const int wn   = warp >> 2;
    const int lq   = lane & 3;
    const int row0 = blockIdx.x * 64;
    const int r0l  = wm * 16 + (lane >> 2);

    const float f2max = fdec(g_f2max_bits);
    const float f10 = g_f1[row0 + r0l];
    const float f11 = g_f1[row0 + r0l + 8];
    float tt;
    tt = f10 + f2max; const float Cr0 = tt > 0.f ? tt : ALPHA_S * tt;
    tt = f11 + f2max; const float Cr1 = tt > 0.f ? tt : ALPHA_S * tt;
    const float c1p0 = __expf(f10 - Cr0), c1n0 = __expf(ALPHA_S * f10 - Cr0);
    const float c1p1 = __expf(f11 - Cr1), c1n1 = __expf(ALPHA_S * f11 - Cr1);
    float psum0 = 0.f, psum1 = 0.f;

    const uint32_t* mrow0 = g_mask + (size_t)(row0 + r0l) * 256;
    const uint32_t* mrow1 = g_mask + (size_t)(row0 + r0l + 8) * 256;

    float acc[8][4];
    #pragma unroll
    for (int j = 0; j < 8; j++)
        #pragma unroll
        for (int q = 0; q < 4; q++) acc[j][q] = 0.0f;

    for (int c = 0; c < 128; c++) {
        const uint64_t m0 = *(const uint64_t*)(mrow0 + c * 2);
        const uint64_t m1 = *(const uint64_t*)(mrow1 + c * 2);
        const float4* tb = (const float4*)(g_tab2 + c * 64);
        const uint4* bp = (const uint4*)g_Bfrag + ((size_t)(c * 4 + wn) * 16) * 32 + lane;

        #pragma unroll
        for (int ks = 0; ks < 4; ks++) {
            // B frags: 4 x LDG.128, lane-coalesced, L1-broadcast across wm warps
            uint4 q0 = __ldg(bp + (ks * 4 + 0) * 32);
            uint4 q1 = __ldg(bp + (ks * 4 + 1) * 32);
            uint4 q2 = __ldg(bp + (ks * 4 + 2) * 32);
            uint4 q3 = __ldg(bp + (ks * 4 + 3) * 32);

            // A frags (leaky-max identity), overlaps the B LDG latency
            const int colb = ks * 16 + 2 * lq;
            float4 ta = __ldg(tb + (colb >> 1));
            float4 tc = __ldg(tb + ((colb + 8) >> 1));
            uint32_t b0 = (uint32_t)(m0 >> colb);
            uint32_t b1 = (uint32_t)(m1 >> colb);
            float p00 = (b0 & 1u)     ? fmaxf(c1p0 * ta.x, c1n0 * ta.y) : 0.f;
            float p01 = (b0 & 2u)     ? fmaxf(c1p0 * ta.z, c1n0 * ta.w) : 0.f;
            float p08 = (b0 & 0x100u) ? fmaxf(c1p0 * tc.x, c1n0 * tc.y) : 0.f;
            float p09 = (b0 & 0x200u) ? fmaxf(c1p0 * tc.z, c1n0 * tc.w) : 0.f;
            float p10 = (b1 & 1u)     ? fmaxf(c1p1 * ta.x, c1n1 * ta.y) : 0.f;
            float p11 = (b1 & 2u)     ? fmaxf(c1p1 * ta.z, c1n1 * ta.w) : 0.f;
            float p18 = (b1 & 0x100u) ? fmaxf(c1p1 * tc.x, c1n1 * tc.y) : 0.f;
            float p19 = (b1 & 0x200u) ? fmaxf(c1p1 * tc.z, c1n1 * tc.w) : 0.f;
            uint32_t af[4];
            af[0] = pack2(p00, p01);
            af[1] = pack2(p10, p11);
            af[2] = pack2(p08, p09);
            af[3] = pack2(p18, p19);
            if (wn == 0) {
                psum0 += (p00 + p01) + (p08 + p09);
                psum1 += (p10 + p11) + (p18 + p19);
            }

            uint32_t bh[16] = { q0.x, q0.y, q0.z, q0.w,
                                q1.x, q1.y, q1.z, q1.w,
                                q2.x, q2.y, q2.z, q2.w,
                                q3.x, q3.y, q3.z, q3.w };
            #pragma unroll
            for (int nt = 0; nt < 8; nt++)
                mma_fp16(acc[nt], af, bh + 2 * nt);
        }
    }

    // ---- rowsums (single barrier in the whole kernel) ----
    if (wn == 0) {
        psum0 += __shfl_xor_sync(0xffffffffu, psum0, 1);
        psum0 += __shfl_xor_sync(0xffffffffu, psum0, 2);
        psum1 += __shfl_xor_sync(0xffffffffu, psum1, 1);
        psum1 += __shfl_xor_sync(0xffffffffu, psum1, 2);
        if (lq == 0) {
            rs[r0l]     = psum0;
            rs[r0l + 8] = psum1;
        }
    }
    __syncthreads();

    const float invA = 1.0f / rs[r0l];
    const float invB = 1.0f / rs[r0l + 8];
    #pragma unroll
    for (int nt = 0; nt < 8; nt++) {
        int cc = wn * 64 + nt * 8 + lq * 2;
        float v0 = acc[nt][0] * invA;
        float v1 = acc[nt][1] * invA;
        float v2 = acc[nt][2] * invB;
        float v3 = acc[nt][3] * invB;
        float2 oA = { v0 > 0.f ? v0 : expm1f(v0), v1 > 0.f ? v1 : expm1f(v1) };
        float2 oB = { v2 > 0.f ? v2 : expm1f(v2), v3 > 0.f ? v3 : expm1f(v3) };
        *(float2*)(out + (size_t)(row0 + r0l) * FD + cc) = oA;
        *(float2*)(out + (size_t)(row0 + r0l + 8) * FD + cc) = oB;
    }
}

// ------- f1/f2 partials: coalesced WhT row reads, 8 n-slices ----------
__global__ void __launch_bounds__(256) f1f2_kernel(const float* __restrict__ a)
{
    const int tid   = threadIdx.x;
    const int mblk  = blockIdx.x >> 3;
    const int slice = blockIdx.x & 7;
    const int m     = mblk * 256 + tid;

    float s1 = 0.0f, s2 = 0.0f;
    #pragma unroll 8
    for (int i = 0; i < 32; i++) {
        int n = slice * 32 + i;
        float v = __half2float(g_WhThi[(size_t)n * NN + m]) +
                  __half2float(g_WhTlo[(size_t)n * NN + m]);
        s1 = fmaf(v, __ldg(a + n),      s1);
        s2 = fmaf(v, __ldg(a + FD + n), s2);
    }
    g_f1p[slice * NN + m] = s1;
    g_f2p[slice * NN + m] = s2;
}

// ------- combine partials + exp tables + global f2 max -------
__global__ void __launch_bounds__(256) tab_kernel()
{
    __shared__ float red[256];
    int tid = threadIdx.x;
    int m = blockIdx.x * 256 + tid;
    float f1 = 0.f, f2 = 0.f;
    #pragma unroll
    for (int s = 0; s < 8; s++) {
        f1 += g_f1p[s * NN + m];
        f2 += g_f2p[s * NN + m];
    }
    g_f1[m] = f1;
    float s2c = fminf(f2, 60.f);
    g_tab2[m] = make_float2(__expf(s2c), __expf(ALPHA_S * s2c));

    red[tid] = f2; __syncthreads();
    #pragma unroll
    for (int s = 128; s > 0; s >>= 1) {
        if (tid < s) red[tid] = fmaxf(red[tid], red[tid + s]);
        __syncthreads();
    }
    if (tid == 0) atomicMax(&g_f2max_bits, fkey(red[0]));
}

// ---------------- launch ----------------
extern "C" void kernel_launch(void* const* d_in, const int* in_sizes, int n_in,
                              void* d_out, int out_size)
{
    const float* h   = (const float*)d_in[0];
    const int*   adj = (const int*)  d_in[1];
    const float* W   = (const float*)d_in[3];
    const float* a   = (const float*)d_in[4];
    float* out = (float*)d_out;

    __nv_bfloat16 *phhi, *phlo, *pWThi, *pWTlo;
    __half *pWhThi, *pWhTlo;
    cudaGetSymbolAddress((void**)&phhi,   g_hhi);
    cudaGetSymbolAddress((void**)&phlo,   g_hlo);
    cudaGetSymbolAddress((void**)&pWThi,  g_WThi);
    cudaGetSymbolAddress((void**)&pWTlo,  g_WTlo);
    cudaGetSymbolAddress((void**)&pWhThi, g_WhThi);
    cudaGetSymbolAddress((void**)&pWhTlo, g_WhTlo);

    cudaFuncSetAttribute(mma_gemm1<8>, cudaFuncAttributeMaxDynamicSharedMemorySize, SMEM1_SZ);
    cudaFuncSetAttribute(bfrag_kernel, cudaFuncAttributeMaxDynamicSharedMemorySize, TF_SMEM);

    // 1) h/W^T splits + adj bitmask pack, merged (both smem-free, DRAM-bound)
    convert_pack<<<NN + FD + NN, 256>>>(h, W, adj);

    // 2) Wh = h@W (bf16 3-pass)
    {
        dim3 grid(NN / 128, FD / 128);
        mma_gemm1<8><<<grid, 256, SMEM1_SZ>>>(
            phhi, phlo, pWThi, pWTlo, pWhThi, pWhTlo);
    }

    // 2b) permute WhThi into MMA-fragment order
    bfrag_kernel<<<128, 512, TF_SMEM>>>();

    // 3) f1/f2 partials (8 slices) then combine + float2 exp tables + f2 max
    f1f2_kernel<<<256, 256>>>(a);
    tab_kernel<<<NN / 256, 256>>>();

    // 4) fused masked-softmax + (P @ Wh)/rowsum + ELU — barrier-free mainloop
    fused_gemm2<<<NN / 64, 512>>>(out);
}